// round 10
// baseline (speedup 1.0000x reference)
#include <cuda_runtime.h>
#include <math.h>

// Problem constants
#define Bb 32
#define Nn 400
#define Cc 720
#define Hh 12
#define HD 60
#define NOUT (2*Cc)          // 1440: only Q and K rows of w_qkv needed
#define M_ROWS (Bb*Nn)       // 12800

__device__ float g_Q[Bb*Hh*Nn*HD];   // (b,h,n,d)
__device__ float g_K[Bb*Hh*Nn*HD];   // (b,h,m,d)
__device__ float g_valid[Bb*Nn];     // 1.0 if roi valid else 0.0

// ---------------------------------------------------------------------------
// Kernel 1: roi_mask[b,n] = (sum_c mask[b,c,n]) != 0   (mask values are >= 0)
// ---------------------------------------------------------------------------
__global__ void roi_mask_kernel(const int* __restrict__ mask) {
    int t = blockIdx.x * blockDim.x + threadIdx.x;
    if (t >= Bb * Nn) return;
    int b = t / Nn;
    int n = t - b * Nn;
    const int* p = mask + (size_t)b * Cc * Nn + n;
    int acc = 0;
    #pragma unroll 8
    for (int c = 0; c < Cc; c++) acc |= p[(size_t)c * Nn];
    g_valid[t] = acc ? 1.0f : 0.0f;
}

// ---------------------------------------------------------------------------
// Kernel 2: QK projection SGEMM.
//   C[m][j] = sum_c x[m][c] * w[j][c]   (m = b*N+n, j in [0,1440))
//   j <  720: Q[b][j/60][n][j%60]
//   j >= 720: K[b][(j-720)/60][n][(j-720)%60]
// Tiling: 128x128 block tile, BK=16, 256 threads, 8x8 register tile,
// gmem->register prefetch to hide load latency.
// ---------------------------------------------------------------------------
#define BM 128
#define BN 128
#define BK 16
#define BMP 132   // +4 pad keeps 16B alignment and reduces store conflicts

__global__ __launch_bounds__(256) void qk_gemm_kernel(const float* __restrict__ x,
                                                      const float* __restrict__ w) {
    __shared__ float As[BK][BMP];
    __shared__ float Bs[BK][BMP];

    const int tid = threadIdx.x;
    const int m0  = blockIdx.y * BM;   // 0..99 tiles, exact
    const int j0  = blockIdx.x * BN;   // 0..11 tiles, last partial
    const int ty  = tid >> 4;          // 0..15
    const int tx  = tid & 15;          // 0..15
    const int lr  = tid >> 2;          // 0..63
    const int lc  = (tid & 3) << 2;    // 0,4,8,12

    const float* Aptr0 = x + (size_t)(m0 + lr) * Cc + lc;
    const float* Aptr1 = Aptr0 + (size_t)64 * Cc;
    const int brow0 = j0 + lr, brow1 = j0 + lr + 64;
    const bool bok0 = brow0 < NOUT, bok1 = brow1 < NOUT;
    const float* Bptr0 = w + (size_t)brow0 * Cc + lc;
    const float* Bptr1 = w + (size_t)brow1 * Cc + lc;
    const float4 z4 = make_float4(0.f, 0.f, 0.f, 0.f);

    float4 ra0, ra1, rb0, rb1;

    // initial tile (kt = 0); K dim = 720 = 45*16, no k-guard needed
    ra0 = *(const float4*)(Aptr0);
    ra1 = *(const float4*)(Aptr1);
    rb0 = bok0 ? *(const float4*)(Bptr0) : z4;
    rb1 = bok1 ? *(const float4*)(Bptr1) : z4;

    As[lc+0][lr] = ra0.x; As[lc+1][lr] = ra0.y; As[lc+2][lr] = ra0.z; As[lc+3][lr] = ra0.w;
    As[lc+0][lr+64] = ra1.x; As[lc+1][lr+64] = ra1.y; As[lc+2][lr+64] = ra1.z; As[lc+3][lr+64] = ra1.w;
    Bs[lc+0][lr] = rb0.x; Bs[lc+1][lr] = rb0.y; Bs[lc+2][lr] = rb0.z; Bs[lc+3][lr] = rb0.w;
    Bs[lc+0][lr+64] = rb1.x; Bs[lc+1][lr+64] = rb1.y; Bs[lc+2][lr+64] = rb1.z; Bs[lc+3][lr+64] = rb1.w;
    __syncthreads();

    float acc[8][8];
    #pragma unroll
    for (int i = 0; i < 8; i++)
        #pragma unroll
        for (int j = 0; j < 8; j++) acc[i][j] = 0.f;

    const int NKT = Cc / BK;  // 45
    for (int kt = 0; kt < NKT; kt++) {
        if (kt < NKT - 1) {
            int off = (kt + 1) * BK;
            ra0 = *(const float4*)(Aptr0 + off);
            ra1 = *(const float4*)(Aptr1 + off);
            rb0 = bok0 ? *(const float4*)(Bptr0 + off) : z4;
            rb1 = bok1 ? *(const float4*)(Bptr1 + off) : z4;
        }
        #pragma unroll
        for (int k = 0; k < BK; k++) {
            float af[8], bf[8];
            *(float4*)&af[0] = *(const float4*)&As[k][ty * 8];
            *(float4*)&af[4] = *(const float4*)&As[k][ty * 8 + 4];
            *(float4*)&bf[0] = *(const float4*)&Bs[k][tx * 8];
            *(float4*)&bf[4] = *(const float4*)&Bs[k][tx * 8 + 4];
            #pragma unroll
            for (int i = 0; i < 8; i++)
                #pragma unroll
                for (int j = 0; j < 8; j++)
                    acc[i][j] = fmaf(af[i], bf[j], acc[i][j]);
        }
        __syncthreads();
        if (kt < NKT - 1) {
            As[lc+0][lr] = ra0.x; As[lc+1][lr] = ra0.y; As[lc+2][lr] = ra0.z; As[lc+3][lr] = ra0.w;
            As[lc+0][lr+64] = ra1.x; As[lc+1][lr+64] = ra1.y; As[lc+2][lr+64] = ra1.z; As[lc+3][lr+64] = ra1.w;
            Bs[lc+0][lr] = rb0.x; Bs[lc+1][lr] = rb0.y; Bs[lc+2][lr] = rb0.z; Bs[lc+3][lr] = rb0.w;
            Bs[lc+0][lr+64] = rb1.x; Bs[lc+1][lr+64] = rb1.y; Bs[lc+2][lr+64] = rb1.z; Bs[lc+3][lr+64] = rb1.w;
            __syncthreads();
        }
    }

    // Epilogue: scatter into Q / K layouts
    #pragma unroll
    for (int i = 0; i < 8; i++) {
        int m = m0 + ty * 8 + i;
        int b = m / Nn;
        int n = m - b * Nn;
        #pragma unroll
        for (int j = 0; j < 8; j++) {
            int col = j0 + tx * 8 + j;
            if (col < NOUT) {
                float v = acc[i][j];
                if (col < Cc) {
                    int h = col / HD, d = col - h * HD;
                    g_Q[(((size_t)b * Hh + h) * Nn + n) * HD + d] = v;
                } else {
                    int c2 = col - Cc;
                    int h = c2 / HD, d = c2 - h * HD;
                    g_K[(((size_t)b * Hh + h) * Nn + n) * HD + d] = v;
                }
            }
        }
    }
}

// ---------------------------------------------------------------------------
// Kernel 3: fused scores + mask + softmax.
// One block per (b,h). Full K (400x60) transposed into smem (KT[d][m]);
// 64-row Q tiles; each thread owns a 4x25 register tile of scores.
// Softmax reduced across the 16 tx-lanes (half-warp shfl).
// ---------------------------------------------------------------------------
#define MT 64
#define SM3_FLOATS (HD*Nn + MT*HD + Nn)   // 24000 + 3840 + 400 = 28240

__global__ __launch_bounds__(256) void attn_softmax_kernel(float* __restrict__ out) {
    extern __shared__ float sm[];
    float* KT = sm;                 // [HD][Nn]
    float* Qs = sm + HD * Nn;       // [MT][HD]
    float* VS = Qs + MT * HD;       // [Nn]

    const float SCALE = 0.12909944487358056f;  // 60^-0.5

    const int bh  = blockIdx.x;      // b*H + h
    const int b   = bh / Hh;
    const int tid = threadIdx.x;
    const int ty  = tid >> 4;        // 0..15 -> 4 rows each
    const int tx  = tid & 15;        // 0..15 -> 25 cols each
    const int m0  = tx * 25;

    const float* Kg = g_K + (size_t)bh * Nn * HD;
    const float* Qg = g_Q + (size_t)bh * Nn * HD;

    // Load K transposed + valid mask
    for (int i = tid; i < Nn * HD; i += 256) {
        int m = i / HD, d = i - m * HD;
        KT[d * Nn + m] = Kg[i];
    }
    for (int i = tid; i < Nn; i += 256) VS[i] = g_valid[b * Nn + i];
    __syncthreads();

    for (int t = 0; t < 7; t++) {          // ceil(400/64) = 7
        int r0 = t * MT;
        // load Q tile
        for (int i = tid; i < MT * HD; i += 256) {
            int r = i / HD;
            int n = r0 + r;
            Qs[i] = (n < Nn) ? Qg[(size_t)n * HD + (i - r * HD)] : 0.f;
        }
        __syncthreads();

        float acc[4][25];
        #pragma unroll
        for (int i = 0; i < 4; i++)
            #pragma unroll
            for (int j = 0; j < 25; j++) acc[i][j] = 0.f;

        #pragma unroll 4
        for (int d = 0; d < HD; d++) {
            float kv[25];
            #pragma unroll
            for (int j = 0; j < 25; j++) kv[j] = KT[d * Nn + m0 + j];
            #pragma unroll
            for (int i = 0; i < 4; i++) {
                float q = Qs[(ty * 4 + i) * HD + d];
                #pragma unroll
                for (int j = 0; j < 25; j++)
                    acc[i][j] = fmaf(q, kv[j], acc[i][j]);
            }
        }

        // mask + softmax + write (per row; reduce across 16 tx lanes)
        #pragma unroll
        for (int i = 0; i < 4; i++) {
            int n = r0 + ty * 4 + i;
            float mx = -3.0e38f;
            #pragma unroll
            for (int j = 0; j < 25; j++) {
                float s = acc[i][j] * SCALE;
                s = (VS[m0 + j] != 0.f) ? s : -10000.0f;
                acc[i][j] = s;
                mx = fmaxf(mx, s);
            }
            #pragma unroll
            for (int o = 8; o > 0; o >>= 1)
                mx = fmaxf(mx, __shfl_xor_sync(0xffffffffu, mx, o));
            float sum = 0.f;
            #pragma unroll
            for (int j = 0; j < 25; j++) {
                float e = __expf(acc[i][j] - mx);
                acc[i][j] = e;
                sum += e;
            }
            #pragma unroll
            for (int o = 8; o > 0; o >>= 1)
                sum += __shfl_xor_sync(0xffffffffu, sum, o);
            float inv = 1.0f / sum;
            if (n < Nn) {
                float* op = out + ((size_t)bh * Nn + n) * Nn + m0;
                #pragma unroll
                for (int j = 0; j < 25; j++) op[j] = acc[i][j] * inv;
            }
        }
        __syncthreads();
    }
}

// ---------------------------------------------------------------------------
extern "C" void kernel_launch(void* const* d_in, const int* in_sizes, int n_in,
                              void* d_out, int out_size) {
    const float* x    = (const float*)d_in[0];  // (B, N, C) f32
    const int*   mask = (const int*)  d_in[1];  // (B, C, N) i32
    const float* w    = (const float*)d_in[2];  // (3C, C)   f32
    float* out = (float*)d_out;                 // (B, H, N, N) f32

    (void)in_sizes; (void)n_in; (void)out_size;

    // opt-in >48KB dynamic smem (idempotent; safe during graph capture)
    cudaFuncSetAttribute(attn_softmax_kernel,
                         cudaFuncAttributeMaxDynamicSharedMemorySize,
                         SM3_FLOATS * (int)sizeof(float));

    roi_mask_kernel<<<(Bb * Nn + 255) / 256, 256>>>(mask);

    dim3 g2((NOUT + BN - 1) / BN, M_ROWS / BM);   // (12, 100)
    qk_gemm_kernel<<<g2, 256>>>(x, w);

    attn_softmax_kernel<<<Bb * Hh, 256, SM3_FLOATS * (int)sizeof(float)>>>(out);
}

// round 11
// speedup vs baseline: 1.0010x; 1.0010x over previous
#include <cuda_runtime.h>
#include <math.h>

// Problem constants
#define Bb 32
#define Nn 400
#define Cc 720
#define Hh 12
#define HD 60
#define NOUT (2*Cc)          // 1440: only Q and K rows of w_qkv needed
#define M_ROWS (Bb*Nn)       // 12800

__device__ float g_Q[Bb*Hh*Nn*HD];   // (b,h,n,d)
__device__ float g_K[Bb*Hh*Nn*HD];   // (b,h,m,d)
__device__ float g_valid[Bb*Nn];     // 1.0 if roi valid else 0.0

// ---------------------------------------------------------------------------
// Kernel 1: roi_mask[b,n] = (sum_c mask[b,c,n]) != 0   (mask values are >= 0)
// ---------------------------------------------------------------------------
__global__ void roi_mask_kernel(const int* __restrict__ mask) {
    int t = blockIdx.x * blockDim.x + threadIdx.x;
    if (t >= Bb * Nn) return;
    int b = t / Nn;
    int n = t - b * Nn;
    const int* p = mask + (size_t)b * Cc * Nn + n;
    int acc = 0;
    #pragma unroll 8
    for (int c = 0; c < Cc; c++) acc |= p[(size_t)c * Nn];
    g_valid[t] = acc ? 1.0f : 0.0f;
}

// ---------------------------------------------------------------------------
// Kernel 2: QK projection SGEMM.
//   C[m][j] = sum_c x[m][c] * w[j][c]   (m = b*N+n, j in [0,1440))
//   j <  720: Q[b][j/60][n][j%60]
//   j >= 720: K[b][(j-720)/60][n][(j-720)%60]
// Tiling: 128x128 block tile, BK=16, 256 threads, 8x8 register tile,
// gmem->register prefetch to hide load latency.
// ---------------------------------------------------------------------------
#define BM 128
#define BN 128
#define BK 16
#define BMP 132   // +4 pad keeps 16B alignment and reduces store conflicts

__global__ __launch_bounds__(256) void qk_gemm_kernel(const float* __restrict__ x,
                                                      const float* __restrict__ w) {
    __shared__ float As[BK][BMP];
    __shared__ float Bs[BK][BMP];

    const int tid = threadIdx.x;
    const int m0  = blockIdx.y * BM;   // 0..99 tiles, exact
    const int j0  = blockIdx.x * BN;   // 0..11 tiles, last partial
    const int ty  = tid >> 4;          // 0..15
    const int tx  = tid & 15;          // 0..15
    const int lr  = tid >> 2;          // 0..63
    const int lc  = (tid & 3) << 2;    // 0,4,8,12

    const float* Aptr0 = x + (size_t)(m0 + lr) * Cc + lc;
    const float* Aptr1 = Aptr0 + (size_t)64 * Cc;
    const int brow0 = j0 + lr, brow1 = j0 + lr + 64;
    const bool bok0 = brow0 < NOUT, bok1 = brow1 < NOUT;
    const float* Bptr0 = w + (size_t)brow0 * Cc + lc;
    const float* Bptr1 = w + (size_t)brow1 * Cc + lc;
    const float4 z4 = make_float4(0.f, 0.f, 0.f, 0.f);

    float4 ra0, ra1, rb0, rb1;

    // initial tile (kt = 0); K dim = 720 = 45*16, no k-guard needed
    ra0 = *(const float4*)(Aptr0);
    ra1 = *(const float4*)(Aptr1);
    rb0 = bok0 ? *(const float4*)(Bptr0) : z4;
    rb1 = bok1 ? *(const float4*)(Bptr1) : z4;

    As[lc+0][lr] = ra0.x; As[lc+1][lr] = ra0.y; As[lc+2][lr] = ra0.z; As[lc+3][lr] = ra0.w;
    As[lc+0][lr+64] = ra1.x; As[lc+1][lr+64] = ra1.y; As[lc+2][lr+64] = ra1.z; As[lc+3][lr+64] = ra1.w;
    Bs[lc+0][lr] = rb0.x; Bs[lc+1][lr] = rb0.y; Bs[lc+2][lr] = rb0.z; Bs[lc+3][lr] = rb0.w;
    Bs[lc+0][lr+64] = rb1.x; Bs[lc+1][lr+64] = rb1.y; Bs[lc+2][lr+64] = rb1.z; Bs[lc+3][lr+64] = rb1.w;
    __syncthreads();

    float acc[8][8];
    #pragma unroll
    for (int i = 0; i < 8; i++)
        #pragma unroll
        for (int j = 0; j < 8; j++) acc[i][j] = 0.f;

    const int NKT = Cc / BK;  // 45
    for (int kt = 0; kt < NKT; kt++) {
        if (kt < NKT - 1) {
            int off = (kt + 1) * BK;
            ra0 = *(const float4*)(Aptr0 + off);
            ra1 = *(const float4*)(Aptr1 + off);
            rb0 = bok0 ? *(const float4*)(Bptr0 + off) : z4;
            rb1 = bok1 ? *(const float4*)(Bptr1 + off) : z4;
        }
        #pragma unroll
        for (int k = 0; k < BK; k++) {
            float af[8], bf[8];
            *(float4*)&af[0] = *(const float4*)&As[k][ty * 8];
            *(float4*)&af[4] = *(const float4*)&As[k][ty * 8 + 4];
            *(float4*)&bf[0] = *(const float4*)&Bs[k][tx * 8];
            *(float4*)&bf[4] = *(const float4*)&Bs[k][tx * 8 + 4];
            #pragma unroll
            for (int i = 0; i < 8; i++)
                #pragma unroll
                for (int j = 0; j < 8; j++)
                    acc[i][j] = fmaf(af[i], bf[j], acc[i][j]);
        }
        __syncthreads();
        if (kt < NKT - 1) {
            As[lc+0][lr] = ra0.x; As[lc+1][lr] = ra0.y; As[lc+2][lr] = ra0.z; As[lc+3][lr] = ra0.w;
            As[lc+0][lr+64] = ra1.x; As[lc+1][lr+64] = ra1.y; As[lc+2][lr+64] = ra1.z; As[lc+3][lr+64] = ra1.w;
            Bs[lc+0][lr] = rb0.x; Bs[lc+1][lr] = rb0.y; Bs[lc+2][lr] = rb0.z; Bs[lc+3][lr] = rb0.w;
            Bs[lc+0][lr+64] = rb1.x; Bs[lc+1][lr+64] = rb1.y; Bs[lc+2][lr+64] = rb1.z; Bs[lc+3][lr+64] = rb1.w;
            __syncthreads();
        }
    }

    // Epilogue: scatter into Q / K layouts
    #pragma unroll
    for (int i = 0; i < 8; i++) {
        int m = m0 + ty * 8 + i;
        int b = m / Nn;
        int n = m - b * Nn;
        #pragma unroll
        for (int j = 0; j < 8; j++) {
            int col = j0 + tx * 8 + j;
            if (col < NOUT) {
                float v = acc[i][j];
                if (col < Cc) {
                    int h = col / HD, d = col - h * HD;
                    g_Q[(((size_t)b * Hh + h) * Nn + n) * HD + d] = v;
                } else {
                    int c2 = col - Cc;
                    int h = c2 / HD, d = c2 - h * HD;
                    g_K[(((size_t)b * Hh + h) * Nn + n) * HD + d] = v;
                }
            }
        }
    }
}

// ---------------------------------------------------------------------------
// Kernel 3: fused scores + mask + softmax.
// One block per (b,h). Full K (400x60) transposed into smem (KT[d][m]);
// 64-row Q tiles; each thread owns a 4x25 register tile of scores.
// Softmax reduced across the 16 tx-lanes (half-warp shfl).
// ---------------------------------------------------------------------------
#define MT 64
#define SM3_FLOATS (HD*Nn + MT*HD + Nn)   // 24000 + 3840 + 400 = 28240

__global__ __launch_bounds__(256) void attn_softmax_kernel(float* __restrict__ out) {
    extern __shared__ float sm[];
    float* KT = sm;                 // [HD][Nn]
    float* Qs = sm + HD * Nn;       // [MT][HD]
    float* VS = Qs + MT * HD;       // [Nn]

    const float SCALE = 0.12909944487358056f;  // 60^-0.5

    const int bh  = blockIdx.x;      // b*H + h
    const int b   = bh / Hh;
    const int tid = threadIdx.x;
    const int ty  = tid >> 4;        // 0..15 -> 4 rows each
    const int tx  = tid & 15;        // 0..15 -> 25 cols each
    const int m0  = tx * 25;

    const float* Kg = g_K + (size_t)bh * Nn * HD;
    const float* Qg = g_Q + (size_t)bh * Nn * HD;

    // Load K transposed + valid mask
    for (int i = tid; i < Nn * HD; i += 256) {
        int m = i / HD, d = i - m * HD;
        KT[d * Nn + m] = Kg[i];
    }
    for (int i = tid; i < Nn; i += 256) VS[i] = g_valid[b * Nn + i];
    __syncthreads();

    for (int t = 0; t < 7; t++) {          // ceil(400/64) = 7
        int r0 = t * MT;
        // load Q tile
        for (int i = tid; i < MT * HD; i += 256) {
            int r = i / HD;
            int n = r0 + r;
            Qs[i] = (n < Nn) ? Qg[(size_t)n * HD + (i - r * HD)] : 0.f;
        }
        __syncthreads();

        float acc[4][25];
        #pragma unroll
        for (int i = 0; i < 4; i++)
            #pragma unroll
            for (int j = 0; j < 25; j++) acc[i][j] = 0.f;

        #pragma unroll 4
        for (int d = 0; d < HD; d++) {
            float kv[25];
            #pragma unroll
            for (int j = 0; j < 25; j++) kv[j] = KT[d * Nn + m0 + j];
            #pragma unroll
            for (int i = 0; i < 4; i++) {
                float q = Qs[(ty * 4 + i) * HD + d];
                #pragma unroll
                for (int j = 0; j < 25; j++)
                    acc[i][j] = fmaf(q, kv[j], acc[i][j]);
            }
        }

        // mask + softmax + write (per row; reduce across 16 tx lanes)
        #pragma unroll
        for (int i = 0; i < 4; i++) {
            int n = r0 + ty * 4 + i;
            float mx = -3.0e38f;
            #pragma unroll
            for (int j = 0; j < 25; j++) {
                float s = acc[i][j] * SCALE;
                s = (VS[m0 + j] != 0.f) ? s : -10000.0f;
                acc[i][j] = s;
                mx = fmaxf(mx, s);
            }
            #pragma unroll
            for (int o = 8; o > 0; o >>= 1)
                mx = fmaxf(mx, __shfl_xor_sync(0xffffffffu, mx, o));
            float sum = 0.f;
            #pragma unroll
            for (int j = 0; j < 25; j++) {
                float e = __expf(acc[i][j] - mx);
                acc[i][j] = e;
                sum += e;
            }
            #pragma unroll
            for (int o = 8; o > 0; o >>= 1)
                sum += __shfl_xor_sync(0xffffffffu, sum, o);
            float inv = 1.0f / sum;
            if (n < Nn) {
                float* op = out + ((size_t)bh * Nn + n) * Nn + m0;
                #pragma unroll
                for (int j = 0; j < 25; j++) op[j] = acc[i][j] * inv;
            }
        }
        __syncthreads();
    }
}

// ---------------------------------------------------------------------------
extern "C" void kernel_launch(void* const* d_in, const int* in_sizes, int n_in,
                              void* d_out, int out_size) {
    const float* x    = (const float*)d_in[0];  // (B, N, C) f32
    const int*   mask = (const int*)  d_in[1];  // (B, C, N) i32
    const float* w    = (const float*)d_in[2];  // (3C, C)   f32
    float* out = (float*)d_out;                 // (B, H, N, N) f32

    (void)in_sizes; (void)n_in; (void)out_size;

    // opt-in >48KB dynamic smem (idempotent; safe during graph capture)
    cudaFuncSetAttribute(attn_softmax_kernel,
                         cudaFuncAttributeMaxDynamicSharedMemorySize,
                         SM3_FLOATS * (int)sizeof(float));

    roi_mask_kernel<<<(Bb * Nn + 255) / 256, 256>>>(mask);

    dim3 g2((NOUT + BN - 1) / BN, M_ROWS / BM);   // (12, 100)
    qk_gemm_kernel<<<g2, 256>>>(x, w);

    attn_softmax_kernel<<<Bb * Hh, 256, SM3_FLOATS * (int)sizeof(float)>>>(out);
}